// round 3
// baseline (speedup 1.0000x reference)
#include <cuda_runtime.h>
#include <stdint.h>

// Problem constants (reference: NY=NX=512, C=64, N=120000)
#define NXD      512
#define HW       (512 * 512)        // 262144 BEV cells
#define CCH      64                 // channels
#define CELLS4   (HW / 4)           // 65536 cell-quads
#define NMAX     120000
#define CHUNKS   4                  // channel chunks per cell-quad (16 ch each)

// Self-validating inverse map (no init pass needed):
//   g_inv[j]  = candidate pillar index for cell j (every historical value is
//               a valid index in [0, N), incl. the zero-initialized state)
//   g_cell[p] = flat cell of pillar p, rewritten every launch
// gather accepts g_inv[j] = p  iff  g_cell[p] == j. Stale entries only pass
// when they are also correct, so output is identical from any prior state.
__device__ int   g_inv[HW];
__device__ int   g_cell[NMAX];
__device__ float g_zero[CCH];       // static zero row for empty cells

// ---------------------------------------------------------------------------
// Kernel 1: scatter pillar ids + record each pillar's cell
// ---------------------------------------------------------------------------
__global__ void k_scatter_idx(const int* __restrict__ coords, int n) {
    int p = blockIdx.x * blockDim.x + threadIdx.x;
    if (p < n) {
        int y = coords[3 * p + 1];
        int x = coords[3 * p + 2];
        int j = y * NXD + x;
        g_inv[j]  = p;
        g_cell[p] = j;
    }
}

// ---------------------------------------------------------------------------
// Kernel 2: gather. One thread owns 4 consecutive cells x 16 channels.
//   262144 threads (4x R2) -> ~55 warps/SM, latency hidden by warp count.
//   j4 is the fastest-varying thread coordinate -> STG.128 fully coalesced.
// ---------------------------------------------------------------------------
__global__ void __launch_bounds__(256) k_gather(const float* __restrict__ vf,
                                                float* __restrict__ out) {
    int tid   = blockIdx.x * blockDim.x + threadIdx.x;  // 0 .. CELLS4*CHUNKS-1
    int j4    = tid & (CELLS4 - 1);                     // cell-quad index
    int chunk = tid >> 16;                              // channel chunk 0..3
    int j     = j4 * 4;

    int4 pv = __ldg(reinterpret_cast<const int4*>(g_inv) + j4);

    bool v0 = (__ldg(&g_cell[pv.x]) == j + 0);
    bool v1 = (__ldg(&g_cell[pv.y]) == j + 1);
    bool v2 = (__ldg(&g_cell[pv.z]) == j + 2);
    bool v3 = (__ldg(&g_cell[pv.w]) == j + 3);

    const float4* r0 = v0 ? reinterpret_cast<const float4*>(vf + (size_t)pv.x * CCH)
                          : reinterpret_cast<const float4*>(g_zero);
    const float4* r1 = v1 ? reinterpret_cast<const float4*>(vf + (size_t)pv.y * CCH)
                          : reinterpret_cast<const float4*>(g_zero);
    const float4* r2 = v2 ? reinterpret_cast<const float4*>(vf + (size_t)pv.z * CCH)
                          : reinterpret_cast<const float4*>(g_zero);
    const float4* r3 = v3 ? reinterpret_cast<const float4*>(vf + (size_t)pv.w * CCH)
                          : reinterpret_cast<const float4*>(g_zero);

    float4* out4 = reinterpret_cast<float4*>(out);
    int cg0 = chunk * (CCH / 4 / CHUNKS);               // 4 channel-groups each

    #pragma unroll
    for (int k = 0; k < CCH / 4 / CHUNKS; k++) {
        int cg = cg0 + k;
        float4 a = __ldg(r0 + cg);   // channels 4cg..4cg+3, cell j+0
        float4 b = __ldg(r1 + cg);
        float4 c = __ldg(r2 + cg);
        float4 d = __ldg(r3 + cg);

        // register transpose: rows = channels, cols = cells
        float4 w0 = make_float4(a.x, b.x, c.x, d.x);
        float4 w1 = make_float4(a.y, b.y, c.y, d.y);
        float4 w2 = make_float4(a.z, b.z, c.z, d.z);
        float4 w3 = make_float4(a.w, b.w, c.w, d.w);

        // out[(4cg+k)*HW + j .. j+3]  ->  out4[(4cg+k)*CELLS4 + j4]
        out4[(size_t)(4 * cg + 0) * CELLS4 + j4] = w0;
        out4[(size_t)(4 * cg + 1) * CELLS4 + j4] = w1;
        out4[(size_t)(4 * cg + 2) * CELLS4 + j4] = w2;
        out4[(size_t)(4 * cg + 3) * CELLS4 + j4] = w3;
    }
}

// ---------------------------------------------------------------------------
extern "C" void kernel_launch(void* const* d_in, const int* in_sizes, int n_in,
                              void* d_out, int out_size) {
    const float* vf     = (const float*)d_in[0];   // [N, 64] fp32
    const int*   coords = (const int*)d_in[1];     // [N, 3]  int32
    float*       out    = (float*)d_out;           // [64, 262144] fp32

    int n = in_sizes[1] / 3;                       // N = 120000

    // 1) scatter pillar ids + per-pillar cell record (self-validating)
    k_scatter_idx<<<(n + 255) / 256, 256>>>(coords, n);
    // 2) gather into canvas (zero-fill fused via g_zero + validity check)
    k_gather<<<(CELLS4 * CHUNKS + 255) / 256, 256>>>(vf, out);
}